// round 2
// baseline (speedup 1.0000x reference)
#include <cuda_runtime.h>
#include <cuda_bf16.h>
#include <math.h>

// Problem constants
#define MM      6          // truncation level
#define DD      5          // path dimension
#define LTOT    19530      // signature length
#define LTOT2   9765       // LTOT / 2 (float2 units)
#define BB      64
#define SS      32
#define NROWS   (BB * SS)  // 2048
#define NBISECT 100

// Scratch (no allocations allowed)
__device__ float g_sums[NROWS * 8];  // per-row per-level squared sums [row][0..5]
__device__ float g_pw[NROWS * 8];    // per-row root powers [row][k] = root^k, k=0..6 (7 used)

// Level segment boundaries (in float elements): level k occupies [off[k-1], off[k])
__device__ __constant__ int c_off[7] = {0, 5, 30, 155, 780, 3905, 19530};

// -------------------- Kernel 1: per-row per-level squared sums --------------------
__global__ __launch_bounds__(256) void k_levelsums(const float* __restrict__ sig) {
    const int row = blockIdx.x;            // (b*S + s)
    const float* __restrict__ x = sig + (size_t)row * LTOT;

    float acc[6] = {0.f, 0.f, 0.f, 0.f, 0.f, 0.f};

    // Segmented loops: no per-element level test; contiguous coalesced loads.
    #pragma unroll
    for (int k = 0; k < 6; k++) {
        const int lo = c_off[k], hi = c_off[k + 1];
        #pragma unroll 4
        for (int i = lo + threadIdx.x; i < hi; i += 256) {
            float v = x[i];
            acc[k] = fmaf(v, v, acc[k]);
        }
    }

    // Block reduce 6 values
    __shared__ float sm[8][8];
    const int lane = threadIdx.x & 31;
    const int w    = threadIdx.x >> 5;
    #pragma unroll
    for (int k = 0; k < 6; k++) {
        float v = acc[k];
        #pragma unroll
        for (int o = 16; o > 0; o >>= 1) v += __shfl_down_sync(0xffffffffu, v, o);
        if (lane == 0) sm[w][k] = v;
    }
    __syncthreads();
    if (w == 0 && lane < 6) {
        float t = 0.f;
        #pragma unroll
        for (int i = 0; i < 8; i++) t += sm[i][lane];
        g_sums[row * 8 + lane] = t;
    }
}

// -------------------- Kernel 2: bisection root solve + powers --------------------
// phi(x) = x for x <= C, else C + C^(1+a)(C^-a - x^-a)/a ; C=4, a=1 => 8 - 16/x
__global__ __launch_bounds__(256) void k_bisect() {
    const int row = blockIdx.x * 256 + threadIdx.x;
    if (row >= NROWS) return;

    float c[7];
    float total = 0.f;
    #pragma unroll
    for (int k = 1; k <= 6; k++) {
        c[k] = g_sums[row * 8 + (k - 1)];
        total += c[k];
    }
    const float nq  = 1.f + total;
    const float phi = (nq > 4.f) ? (8.f - 16.f / nq) : nq;
    c[0] = 1.f - phi;

    bool fin = true;
    #pragma unroll
    for (int k = 0; k < 7; k++) fin = fin && isfinite(c[k]);

    float lo = 0.f, hi = 2.f;
    #pragma unroll 4
    for (int it = 0; it < NBISECT; it++) {
        const float mid = 0.5f * (lo + hi);
        const float u   = mid * mid;
        float p = c[6];
        #pragma unroll
        for (int k = 5; k >= 0; k--) p = fmaf(p, u, c[k]);
        const bool neg = p < 0.f;
        lo = neg ? mid : lo;
        hi = neg ? hi  : mid;
    }
    float root = 0.5f * (lo + hi);
    if (!fin) root = 0.f;
    root = fminf(root, 1.f);

    float p = 1.f;
    g_pw[row * 8 + 0] = 1.f;
    #pragma unroll
    for (int k = 1; k <= 6; k++) {
        p *= root;
        g_pw[row * 8 + k] = p;
    }
    g_pw[row * 8 + 7] = 0.f;
}

// -------------------- Kernel 3: scale by root^level and mean over S --------------------
__device__ __forceinline__ int level_of(int idx) {
    // idx in [0, LTOT)
    if (idx < 5)    return 1;
    if (idx < 30)   return 2;
    if (idx < 155)  return 3;
    if (idx < 780)  return 4;
    if (idx < 3905) return 5;
    return 6;
}

__global__ __launch_bounds__(256) void k_scale(const float* __restrict__ sig,
                                               float* __restrict__ out) {
    const int b = blockIdx.y;
    const int j = blockIdx.x * 256 + threadIdx.x;   // float2 index within row

    __shared__ float spw[SS * 8];                    // powers for this batch's 32 samples
    // 256 threads load exactly 32*8 floats
    spw[threadIdx.x] = g_pw[(size_t)b * SS * 8 + threadIdx.x];
    __syncthreads();

    if (j >= LTOT2) return;

    const int l0 = 2 * j, l1 = 2 * j + 1;
    const int lv0 = level_of(l0);
    const int lv1 = level_of(l1);

    const float2* __restrict__ s2 = (const float2*)sig + (size_t)b * SS * LTOT2 + j;

    float a0 = 0.f, a1 = 0.f;
    #pragma unroll 8
    for (int s = 0; s < SS; s++) {
        const float2 v = s2[(size_t)s * LTOT2];
        a0 = fmaf(v.x, spw[s * 8 + lv0], a0);
        a1 = fmaf(v.y, spw[s * 8 + lv1], a1);
    }

    const float inv = 1.f / (float)SS;
    ((float2*)out)[(size_t)b * LTOT2 + j] = make_float2(a0 * inv, a1 * inv);
}

// -------------------- launch --------------------
extern "C" void kernel_launch(void* const* d_in, const int* in_sizes, int n_in,
                              void* d_out, int out_size) {
    const float* sig = (const float*)d_in[0];
    float* out = (float*)d_out;

    k_levelsums<<<NROWS, 256>>>(sig);
    k_bisect<<<(NROWS + 255) / 256, 256>>>();
    dim3 g3((LTOT2 + 255) / 256, BB);
    k_scale<<<g3, 256>>>(sig, out);
}

// round 3
// speedup vs baseline: 1.1833x; 1.1833x over previous
#include <cuda_runtime.h>
#include <cuda_bf16.h>
#include <math.h>

#define LTOT    19530
#define BB      64
#define SS      32
#define NROWS   (BB * SS)   // 2048
#define NBISECT 64
#define N4      4882        // full float4 groups per row (4*4882 = 19528)

// Scratch (__device__ globals: allocation-guard compliant)
__device__ float g_pw[NROWS * 8];   // per-row root powers [row][k] = root^k, k=0..7

// ---------------------------------------------------------------------------
// Kernel 1: per-row per-level squared sums (vectorized) + fused bisection
// ---------------------------------------------------------------------------
__device__ __forceinline__ void vec_sq_sum(const float* __restrict__ x,
                                           int lo, int hi, int p,
                                           int tid, float& acc) {
    // first index >= lo with idx % 4 == p  (so x+a is 16B aligned)
    int a = lo + ((((p - lo) % 4) + 4) % 4);
    // scalar head (< 4 elements)
    if (tid < a - lo) { float v = x[lo + tid]; acc = fmaf(v, v, acc); }
    const int nv = (hi - a) >> 2;
    const float4* __restrict__ xv = (const float4*)(x + a);
    #pragma unroll 4
    for (int i = tid; i < nv; i += 256) {
        float4 v = xv[i];
        acc = fmaf(v.x, v.x, acc);
        acc = fmaf(v.y, v.y, acc);
        acc = fmaf(v.z, v.z, acc);
        acc = fmaf(v.w, v.w, acc);
    }
    // scalar tail (< 4 elements)
    const int t0 = a + 4 * nv;
    if (tid < hi - t0) { float v = x[t0 + tid]; acc = fmaf(v, v, acc); }
}

__global__ __launch_bounds__(256) void k_levelsums(const float* __restrict__ sig) {
    const int row = blockIdx.x;
    const int tid = threadIdx.x;
    const float* __restrict__ x = sig + (size_t)row * LTOT;

    float acc[6] = {0.f, 0.f, 0.f, 0.f, 0.f, 0.f};

    // levels 1-4: [0,5),[5,30),[30,155),[155,780) — scalar (tiny)
    const int off[5] = {0, 5, 30, 155, 780};
    #pragma unroll
    for (int k = 0; k < 4; k++) {
        for (int i = off[k] + tid; i < off[k + 1]; i += 256) {
            float v = x[i];
            acc[k] = fmaf(v, v, acc[k]);
        }
    }

    // levels 5,6: vectorized. Row byte base = row*78120; 78120 % 16 == 8,
    // so aligned float4 phase is idx%4 == 0 (even row) or 2 (odd row).
    const int p = (row & 1) ? 2 : 0;
    vec_sq_sum(x, 780,  3905,  p, tid, acc[4]);
    vec_sq_sum(x, 3905, LTOT,  p, tid, acc[5]);

    // block reduce 6 sums
    __shared__ float sm[8][8];
    __shared__ float totals[8];
    const int lane = tid & 31;
    const int w    = tid >> 5;
    #pragma unroll
    for (int k = 0; k < 6; k++) {
        float v = acc[k];
        #pragma unroll
        for (int o = 16; o > 0; o >>= 1) v += __shfl_down_sync(0xffffffffu, v, o);
        if (lane == 0) sm[w][k] = v;
    }
    __syncthreads();
    if (w == 0) {
        if (lane < 6) {
            float t = 0.f;
            #pragma unroll
            for (int i = 0; i < 8; i++) t += sm[i][lane];
            totals[lane] = t;
        }
        __syncwarp();
        if (lane == 0) {
            // ---- fused bisection (phi: C=4, a=1 -> phi(x)=8-16/x for x>4) ----
            float c[7];
            float total = 0.f;
            #pragma unroll
            for (int k = 1; k <= 6; k++) { c[k] = totals[k - 1]; total += c[k]; }
            const float nq  = 1.f + total;
            const float phi = (nq > 4.f) ? (8.f - 16.f / nq) : nq;
            c[0] = 1.f - phi;

            bool fin = true;
            #pragma unroll
            for (int k = 0; k < 7; k++) fin = fin && isfinite(c[k]);

            float lo = 0.f, hi = 2.f;
            #pragma unroll 4
            for (int it = 0; it < NBISECT; it++) {
                const float mid = 0.5f * (lo + hi);
                const float u   = mid * mid;
                float pz = c[6];
                #pragma unroll
                for (int k = 5; k >= 0; k--) pz = fmaf(pz, u, c[k]);
                const bool neg = pz < 0.f;
                lo = neg ? mid : lo;
                hi = neg ? hi  : mid;
            }
            float root = 0.5f * (lo + hi);
            if (!fin) root = 0.f;
            root = fminf(root, 1.f);

            float pw = 1.f;
            g_pw[row * 8 + 0] = 1.f;
            #pragma unroll
            for (int k = 1; k <= 6; k++) { pw *= root; g_pw[row * 8 + k] = pw; }
            g_pw[row * 8 + 7] = 0.f;
        }
    }
}

// ---------------------------------------------------------------------------
// Kernel 2: scale by root^level and mean over S (vectorized, 4 elems/thread)
// ---------------------------------------------------------------------------
__device__ __forceinline__ int level_of(int idx) {
    if (idx < 5)    return 1;
    if (idx < 30)   return 2;
    if (idx < 155)  return 3;
    if (idx < 780)  return 4;
    if (idx < 3905) return 5;
    return 6;
}

__global__ __launch_bounds__(256) void k_scale(const float* __restrict__ sig,
                                               float* __restrict__ out) {
    const int b = blockIdx.y;

    __shared__ float spw[SS * 8];   // powers for this batch's 32 samples (256 floats)
    spw[threadIdx.x] = g_pw[(size_t)b * SS * 8 + threadIdx.x];
    __syncthreads();

    const int j4 = blockIdx.x * 256 + threadIdx.x;  // float4 group within row
    if (j4 > N4) return;

    const float* __restrict__ base = sig + (size_t)b * SS * LTOT;
    const float inv = 1.f / (float)SS;

    if (j4 < N4) {
        const int e0 = 4 * j4;
        const int lv0 = level_of(e0);
        const int lv1 = level_of(e0 + 1);
        const int lv2 = level_of(e0 + 2);
        const int lv3 = level_of(e0 + 3);

        float a0 = 0.f, a1 = 0.f, a2 = 0.f, a3 = 0.f;
        // pair loop: even-s rows are 16B aligned (LDG.128); odd-s rows are 8B
        // aligned only (two LDG.64).  row byte base = (b*32+s)*78120, 78120%16==8.
        #pragma unroll 4
        for (int s0 = 0; s0 < SS; s0 += 2) {
            const float* r0 = base + (size_t)s0 * LTOT + e0;
            const float4 v  = *(const float4*)r0;
            a0 = fmaf(v.x, spw[s0 * 8 + lv0], a0);
            a1 = fmaf(v.y, spw[s0 * 8 + lv1], a1);
            a2 = fmaf(v.z, spw[s0 * 8 + lv2], a2);
            a3 = fmaf(v.w, spw[s0 * 8 + lv3], a3);

            const float* r1 = base + (size_t)(s0 + 1) * LTOT + e0;
            const float2 u0 = *(const float2*)r1;
            const float2 u1 = *(const float2*)(r1 + 2);
            a0 = fmaf(u0.x, spw[(s0 + 1) * 8 + lv0], a0);
            a1 = fmaf(u0.y, spw[(s0 + 1) * 8 + lv1], a1);
            a2 = fmaf(u1.x, spw[(s0 + 1) * 8 + lv2], a2);
            a3 = fmaf(u1.y, spw[(s0 + 1) * 8 + lv3], a3);
        }
        float* o = out + (size_t)b * LTOT + e0;       // 8B aligned always
        *(float2*)o       = make_float2(a0 * inv, a1 * inv);
        *(float2*)(o + 2) = make_float2(a2 * inv, a3 * inv);
    } else {
        // tail: elements 19528, 19529 (level 6)
        const int e0 = 4 * N4;
        float a0 = 0.f, a1 = 0.f;
        #pragma unroll 8
        for (int s = 0; s < SS; s++) {
            const float2 v = *(const float2*)(base + (size_t)s * LTOT + e0);
            const float  w = spw[s * 8 + 6];
            a0 = fmaf(v.x, w, a0);
            a1 = fmaf(v.y, w, a1);
        }
        float* o = out + (size_t)b * LTOT + e0;
        *(float2*)o = make_float2(a0 * inv, a1 * inv);
    }
}

// ---------------------------------------------------------------------------
extern "C" void kernel_launch(void* const* d_in, const int* in_sizes, int n_in,
                              void* d_out, int out_size) {
    const float* sig = (const float*)d_in[0];
    float* out = (float*)d_out;

    k_levelsums<<<NROWS, 256>>>(sig);
    dim3 g2((N4 + 1 + 255) / 256, BB);   // 20 x 64 blocks
    k_scale<<<g2, 256>>>(sig, out);
}